// round 14
// baseline (speedup 1.0000x reference)
#include <cuda_runtime.h>
#include <cuda_bf16.h>

// Problem constants: IN=4, H=30, OUT=1, N_UNIT=100, B=262144
#define NU    100
#define HH    30
#define NT    256          // threads per block (8 warps)
#define RPB   NT           // 1 row per thread -> 256 rows per block

// ---------------------------------------------------------------------------
// Warp-transposed fused kernel:
//  * per-block merit-order setup (redundant, deterministic)
//  * each warp owns 32 rows; lane r computes layer-1 for its row;
//    lane L accumulates h2[k=L] for all 32 rows (acc[32] in registers);
//    W2 read as conflict-free distinct LDS.32 (1 wavefront per unit);
//    h1 broadcast lane->lanes via __shfl (no L1 traffic)
//  * butterfly-reduced output layer, register-cached coalesced store epilogue
// ---------------------------------------------------------------------------
__global__ __launch_bounds__(NT, 4)
void mlp_dispatch_kernel(const float4* __restrict__ x,     // [B,4] as float4
                         const float*  __restrict__ Cost,  // [100]
                         const float*  __restrict__ Pmax,  // [100]
                         const float*  __restrict__ Pd,    // [100]
                         const float*  __restrict__ wcap,  // [1]
                         const float*  __restrict__ W1,    // [4,30]
                         const float*  __restrict__ b1,    // [30]
                         const float*  __restrict__ W2,    // [30,30]
                         const float*  __restrict__ b2,    // [30]
                         const float*  __restrict__ W3,    // [30,1]
                         const float*  __restrict__ b3,    // [1]
                         float*        __restrict__ out)   // [B,100]
{
    __shared__ alignas(16) float4 sW1t[HH];      // sW1t[i] = W1[0..3][i] (transposed)
    __shared__ alignas(16) float  sb1[HH];
    __shared__ alignas(16) float  sW2[HH * 32];  // row i at sW2[32i], cols 30,31 = 0
    __shared__ alignas(16) float  sb2p[32];      // padded with zeros
    __shared__ alignas(16) float  sW3p[32];      // padded with zeros
    __shared__ alignas(16) float  sCost[NU];
    __shared__ alignas(16) float  sCum[NU];
    __shared__ alignas(16) float  sPmax[NU];
    __shared__ alignas(16) float  sTd[RPB];
    __shared__ float sB3, sWc, sSum;

    const int tid  = threadIdx.x;
    const int lane = tid & 31;
    const int wid  = tid >> 5;

    // ---- Stage params ----
    for (int i = tid; i < HH * 32; i += NT) {
        int r = i >> 5, c = i & 31;
        sW2[i] = (c < HH) ? W2[r * HH + c] : 0.0f;
    }
    if (tid < 32) {
        sb2p[tid] = (tid < HH) ? b2[tid] : 0.0f;
        sW3p[tid] = (tid < HH) ? W3[tid] : 0.0f;
    }
    if (tid >= 32 && tid < 32 + HH) {
        int i = tid - 32;
        sW1t[i] = make_float4(W1[0 * HH + i], W1[1 * HH + i],
                              W1[2 * HH + i], W1[3 * HH + i]);
        sb1[i] = b1[i];
    }
    if (tid < NU) { sCost[tid] = Cost[tid]; sPmax[tid] = Pmax[tid]; }
    if (tid == 0) { sB3 = b3[0]; sWc = wcap[0]; }
    if (tid >= NT - 32) {          // last warp: parallel sum(Pd)
        int l = tid - (NT - 32);
        float s = 0.0f;
        for (int j = l; j < NU; j += 32) s += Pd[j];
        #pragma unroll
        for (int o = 16; o > 0; o >>= 1)
            s += __shfl_xor_sync(0xFFFFFFFFu, s, o);
        if (l == 0) sSum = s;
    }
    __syncthreads();

    // ---- Merit order (stable argsort closed form), per original unit ----
    if (tid < NU) {
        const float cj = sCost[tid];
        float cum = 0.0f;
        #pragma unroll 4
        for (int k = 0; k < NU; k++) {
            float ck = sCost[k];
            bool cheaper = (ck < cj) || (ck == cj && k < tid);
            if (cheaper) cum += sPmax[k];
        }
        sCum[tid] = cum;
    }

    // ---- each lane loads its own row's x (coalesced 512B per warp) ----
    const float4 xv = x[(long)blockIdx.x * RPB + tid];

    // ---- acc[r] = h2[k=lane] of row (warp row-base + r); init with b2[k] ----
    float acc[32];
    {
        const float bp = sb2p[lane];
        #pragma unroll
        for (int r = 0; r < 32; r++) acc[r] = bp;
    }

    // ---- fused layer-1 + warp-transposed layer-2 ----
    #pragma unroll 3
    for (int i = 0; i < HH; i++) {
        // lane r computes h1[i] of its own row
        const float4 w1 = sW1t[i];
        float a = sb1[i];
        a = fmaf(xv.x, w1.x, a);
        a = fmaf(xv.y, w1.y, a);
        a = fmaf(xv.z, w1.z, a);
        a = fmaf(xv.w, w1.w, a);
        const float h = fmaxf(a, 0.0f);

        // lane L reads W2[i][L]: 32 distinct 4B addresses in one 128B row -> 1 wf
        const float w2l = sW2[i * 32 + lane];

        // broadcast h of each row via shfl; every FMA does 32 useful MACs
        #pragma unroll
        for (int r = 0; r < 32; r++) {
            const float hr = __shfl_sync(0xFFFFFFFFu, h, r);
            acc[r] = fmaf(hr, w2l, acc[r]);
        }
    }

    // ---- output layer: y[row r] = b3 + sum_k relu(h2[k][r]) * W3[k] ----
    const float w3l = sW3p[lane];
    float y = 0.0f;
    #pragma unroll
    for (int r = 0; r < 32; r++) {
        float v = fmaxf(acc[r], 0.0f) * w3l;
        v += __shfl_xor_sync(0xFFFFFFFFu, v, 16);
        v += __shfl_xor_sync(0xFFFFFFFFu, v, 8);
        v += __shfl_xor_sync(0xFFFFFFFFu, v, 4);
        v += __shfl_xor_sync(0xFFFFFFFFu, v, 2);
        v += __shfl_xor_sync(0xFFFFFFFFu, v, 1);
        if (lane == r) y = v;        // lane r keeps y of row r
    }
    sTd[wid * 32 + lane] = sSum - sWc * (y + sB3);
    __syncthreads();

    // ---- dispatch + store: register-cached cu/pm per fixed vec4-column ----
    // 250 active threads: g = t%25 (column group), r0 = t/25 (0..9).
    if (tid < 250) {
        const int g  = tid % 25;
        const int r0 = tid / 25;
        const float4 cu4 = *reinterpret_cast<const float4*>(sCum  + 4 * g);
        const float4 pm4 = *reinterpret_cast<const float4*>(sPmax + 4 * g);
        float4* outv = reinterpret_cast<float4*>(out + (size_t)blockIdx.x * RPB * NU);
        #pragma unroll 4
        for (int it = 0; it < 26; it++) {        // 256 rows, 10 rows per iter
            const int r = r0 + 10 * it;
            if (r < RPB) {
                const float t = sTd[r];
                float4 pq;
                pq.x = fminf(fmaxf(t - cu4.x, 0.0f), pm4.x);
                pq.y = fminf(fmaxf(t - cu4.y, 0.0f), pm4.y);
                pq.z = fminf(fmaxf(t - cu4.z, 0.0f), pm4.z);
                pq.w = fminf(fmaxf(t - cu4.w, 0.0f), pm4.w);
                outv[r * 25 + g] = pq;
            }
        }
    }
}

// ---------------------------------------------------------------------------
// Launch. Input order: x, Cost, Pmax, Pd, w_capacity, W1, b1, W2, b2, W3, b3
// ---------------------------------------------------------------------------
extern "C" void kernel_launch(void* const* d_in, const int* in_sizes, int n_in,
                              void* d_out, int out_size) {
    const float* x     = (const float*)d_in[0];
    const float* Cost  = (const float*)d_in[1];
    const float* Pmax  = (const float*)d_in[2];
    const float* Pd    = (const float*)d_in[3];
    const float* wcap  = (const float*)d_in[4];
    const float* W1    = (const float*)d_in[5];
    const float* b1    = (const float*)d_in[6];
    const float* W2    = (const float*)d_in[7];
    const float* b2    = (const float*)d_in[8];
    const float* W3    = (const float*)d_in[9];
    const float* b3    = (const float*)d_in[10];
    float* out = (float*)d_out;

    const int B = in_sizes[0] / 4;      // x is [B, 4]
    const int blocks = B / RPB;         // 262144 / 256 = 1024

    mlp_dispatch_kernel<<<blocks, NT>>>(
        (const float4*)x, Cost, Pmax, Pd, wcap, W1, b1, W2, b2, W3, b3, out);
}

// round 15
// speedup vs baseline: 1.2880x; 1.2880x over previous
#include <cuda_runtime.h>
#include <cuda_bf16.h>

// Problem constants: IN=4, H=30, OUT=1, N_UNIT=100, B=262144
#define NU    100
#define HH    30
#define NT    256          // threads per block
#define RPT   4            // rows per thread
#define RPB   (NT * RPT)   // 1024 rows per block

typedef unsigned long long u64;

// ---- packed f32x2 helpers (sm_103a) ----
__device__ __forceinline__ u64 ffma2(u64 a, u64 b, u64 c) {
    u64 d;
    asm("fma.rn.f32x2 %0, %1, %2, %3;" : "=l"(d) : "l"(a), "l"(b), "l"(c));
    return d;
}
__device__ __forceinline__ u64 pack2(float x, float y) {
    u64 d;
    asm("mov.b64 %0, {%1, %2};" : "=l"(d) : "f"(x), "f"(y));
    return d;
}
__device__ __forceinline__ float2 unpack2(u64 a) {
    float2 f;
    asm("mov.b64 {%0, %1}, %2;" : "=f"(f.x), "=f"(f.y) : "l"(a));
    return f;
}
__device__ __forceinline__ u64 relu2(u64 a) {
    float2 f = unpack2(a);
    return pack2(fmaxf(f.x, 0.0f), fmaxf(f.y, 0.0f));
}

// ---------------------------------------------------------------------------
// Fused kernel: per-block merit-order setup; 4 rows/thread MLP with 4-way
// k-split (4 k-pairs live per pass -> 32 acc regs; every W2 LDS.128 feeds
// 4 rows); scalar layer-1 recomputed per pass; register-cached store epilogue.
// ---------------------------------------------------------------------------
__global__ __launch_bounds__(NT, 3)
void mlp_dispatch_kernel(const float4* __restrict__ x,     // [B,4] as float4
                         const float*  __restrict__ Cost,  // [100]
                         const float*  __restrict__ Pmax,  // [100]
                         const float*  __restrict__ Pd,    // [100]
                         const float*  __restrict__ wcap,  // [1]
                         const float*  __restrict__ W1,    // [4,30]
                         const float*  __restrict__ b1,    // [30]
                         const float*  __restrict__ W2,    // [30,30]
                         const float*  __restrict__ b2,    // [30]
                         const float*  __restrict__ W3,    // [30,1]
                         const float*  __restrict__ b3,    // [1]
                         float*        __restrict__ out)   // [B,100]
{
    __shared__ alignas(16) float4 sW1t[HH];      // sW1t[i] = W1[0..3][i] (transposed)
    __shared__ alignas(16) float  sb1[HH];
    __shared__ alignas(16) float  sW2[HH * 32];  // rows padded to 32 floats (zeros)
    __shared__ alignas(16) float  sb2p[32];      // padded with zeros
    __shared__ alignas(16) float  sW3p[32];      // padded with zeros
    __shared__ alignas(16) float  sCost[NU];
    __shared__ alignas(16) float  sCum[NU];
    __shared__ alignas(16) float  sPmax[NU];
    __shared__ alignas(16) float  sTd[RPB];
    __shared__ float sB3, sWc, sSum;

    const int tid = threadIdx.x;

    // ---- Stage params ----
    for (int i = tid; i < HH * 32; i += NT) {
        int r = i >> 5, c = i & 31;
        sW2[i] = (c < HH) ? W2[r * HH + c] : 0.0f;
    }
    if (tid < 32) {
        sb2p[tid] = (tid < HH) ? b2[tid] : 0.0f;
        sW3p[tid] = (tid < HH) ? W3[tid] : 0.0f;
    }
    if (tid >= 32 && tid < 32 + HH) {
        int i = tid - 32;
        sW1t[i] = make_float4(W1[0 * HH + i], W1[1 * HH + i],
                              W1[2 * HH + i], W1[3 * HH + i]);
        sb1[i] = b1[i];
    }
    if (tid < NU) { sCost[tid] = Cost[tid]; sPmax[tid] = Pmax[tid]; }
    if (tid == 0) { sB3 = b3[0]; sWc = wcap[0]; }
    if (tid >= NT - 32) {          // last warp: parallel sum(Pd)
        int l = tid - (NT - 32);
        float s = 0.0f;
        for (int j = l; j < NU; j += 32) s += Pd[j];
        #pragma unroll
        for (int o = 16; o > 0; o >>= 1)
            s += __shfl_xor_sync(0xFFFFFFFFu, s, o);
        if (l == 0) sSum = s;
    }
    __syncthreads();

    // ---- Merit order (stable argsort closed form), per original unit ----
    if (tid < NU) {
        const float cj = sCost[tid];
        float cum = 0.0f;
        #pragma unroll 4
        for (int k = 0; k < NU; k++) {
            float ck = sCost[k];
            bool cheaper = (ck < cj) || (ck == cj && k < tid);
            if (cheaper) cum += sPmax[k];
        }
        sCum[tid] = cum;
    }

    // ---- this thread's 4 rows ----
    const long base = (long)blockIdx.x * RPB + 4 * tid;
    const float4 xr0 = x[base];
    const float4 xr1 = x[base + 1];
    const float4 xr2 = x[base + 2];
    const float4 xr3 = x[base + 3];

    // ---- MLP: four k-quarter passes; 4 packed k-pairs live per row ----
    u64 yp0 = pack2(sB3, 0.0f);
    u64 yp1 = pack2(sB3, 0.0f);
    u64 yp2 = pack2(sB3, 0.0f);
    u64 yp3 = pack2(sB3, 0.0f);
    #pragma unroll
    for (int p = 0; p < 4; p++) {
        u64 acc0[4], acc1[4], acc2[4], acc3[4];
        #pragma unroll
        for (int q = 0; q < 4; q++) {
            u64 bp = *reinterpret_cast<const u64*>(&sb2p[8 * p + 2 * q]);
            acc0[q] = bp; acc1[q] = bp; acc2[q] = bp; acc3[q] = bp;
        }
        #pragma unroll
        for (int i = 0; i < HH; i++) {
            // scalar layer-1 unit i for 4 rows (recomputed per pass)
            const float4 w1 = sW1t[i];
            const float  bb = sb1[i];
            float a0 = bb, a1 = bb, a2 = bb, a3 = bb;
            a0 = fmaf(xr0.x, w1.x, a0); a1 = fmaf(xr1.x, w1.x, a1);
            a2 = fmaf(xr2.x, w1.x, a2); a3 = fmaf(xr3.x, w1.x, a3);
            a0 = fmaf(xr0.y, w1.y, a0); a1 = fmaf(xr1.y, w1.y, a1);
            a2 = fmaf(xr2.y, w1.y, a2); a3 = fmaf(xr3.y, w1.y, a3);
            a0 = fmaf(xr0.z, w1.z, a0); a1 = fmaf(xr1.z, w1.z, a1);
            a2 = fmaf(xr2.z, w1.z, a2); a3 = fmaf(xr3.z, w1.z, a3);
            a0 = fmaf(xr0.w, w1.w, a0); a1 = fmaf(xr1.w, w1.w, a1);
            a2 = fmaf(xr2.w, w1.w, a2); a3 = fmaf(xr3.w, w1.w, a3);
            const float h0 = fmaxf(a0, 0.0f);
            const float h1 = fmaxf(a1, 0.0f);
            const float h2 = fmaxf(a2, 0.0f);
            const float h3 = fmaxf(a3, 0.0f);
            const u64 h0d = pack2(h0, h0);
            const u64 h1d = pack2(h1, h1);
            const u64 h2d = pack2(h2, h2);
            const u64 h3d = pack2(h3, h3);

            // this pass's 8 floats of W2 row i (2x LDS.128, shared by 4 rows)
            const float* wrow = &sW2[i * 32 + 8 * p];
            ulonglong2 wva = *reinterpret_cast<const ulonglong2*>(wrow);
            ulonglong2 wvb = *reinterpret_cast<const ulonglong2*>(wrow + 4);
            acc0[0] = ffma2(h0d, wva.x, acc0[0]);
            acc1[0] = ffma2(h1d, wva.x, acc1[0]);
            acc2[0] = ffma2(h2d, wva.x, acc2[0]);
            acc3[0] = ffma2(h3d, wva.x, acc3[0]);
            acc0[1] = ffma2(h0d, wva.y, acc0[1]);
            acc1[1] = ffma2(h1d, wva.y, acc1[1]);
            acc2[1] = ffma2(h2d, wva.y, acc2[1]);
            acc3[1] = ffma2(h3d, wva.y, acc3[1]);
            acc0[2] = ffma2(h0d, wvb.x, acc0[2]);
            acc1[2] = ffma2(h1d, wvb.x, acc1[2]);
            acc2[2] = ffma2(h2d, wvb.x, acc2[2]);
            acc3[2] = ffma2(h3d, wvb.x, acc3[2]);
            acc0[3] = ffma2(h0d, wvb.y, acc0[3]);
            acc1[3] = ffma2(h1d, wvb.y, acc1[3]);
            acc2[3] = ffma2(h2d, wvb.y, acc2[3]);
            acc3[3] = ffma2(h3d, wvb.y, acc3[3]);
        }
        // fold this k-quarter into the output dots
        #pragma unroll
        for (int q = 0; q < 4; q++) {
            u64 w3p = *reinterpret_cast<const u64*>(&sW3p[8 * p + 2 * q]);
            yp0 = ffma2(relu2(acc0[q]), w3p, yp0);
            yp1 = ffma2(relu2(acc1[q]), w3p, yp1);
            yp2 = ffma2(relu2(acc2[q]), w3p, yp2);
            yp3 = ffma2(relu2(acc3[q]), w3p, yp3);
        }
    }
    {
        const float2 y0 = unpack2(yp0);
        const float2 y1 = unpack2(yp1);
        const float2 y2 = unpack2(yp2);
        const float2 y3 = unpack2(yp3);
        sTd[4 * tid]     = sSum - sWc * (y0.x + y0.y);
        sTd[4 * tid + 1] = sSum - sWc * (y1.x + y1.y);
        sTd[4 * tid + 2] = sSum - sWc * (y2.x + y2.y);
        sTd[4 * tid + 3] = sSum - sWc * (y3.x + y3.y);
    }
    __syncthreads();

    // ---- dispatch + store: register-cached cu/pm per fixed vec4-column ----
    // 250 active threads: g = t%25 (column group), r0 = t/25 (0..9).
    if (tid < 250) {
        const int g  = tid % 25;
        const int r0 = tid / 25;
        const float4 cu4 = *reinterpret_cast<const float4*>(sCum  + 4 * g);
        const float4 pm4 = *reinterpret_cast<const float4*>(sPmax + 4 * g);
        float4* outv = reinterpret_cast<float4*>(out + (size_t)blockIdx.x * RPB * NU);
        #pragma unroll 4
        for (int it = 0; it < 103; it++) {       // 1024 rows, 10 rows per iter
            const int r = r0 + 10 * it;
            if (r < RPB) {
                const float t = sTd[r];
                float4 pq;
                pq.x = fminf(fmaxf(t - cu4.x, 0.0f), pm4.x);
                pq.y = fminf(fmaxf(t - cu4.y, 0.0f), pm4.y);
                pq.z = fminf(fmaxf(t - cu4.z, 0.0f), pm4.z);
                pq.w = fminf(fmaxf(t - cu4.w, 0.0f), pm4.w);
                outv[r * 25 + g] = pq;
            }
        }
    }
}

// ---------------------------------------------------------------------------
// Launch. Input order: x, Cost, Pmax, Pd, w_capacity, W1, b1, W2, b2, W3, b3
// ---------------------------------------------------------------------------
extern "C" void kernel_launch(void* const* d_in, const int* in_sizes, int n_in,
                              void* d_out, int out_size) {
    const float* x     = (const float*)d_in[0];
    const float* Cost  = (const float*)d_in[1];
    const float* Pmax  = (const float*)d_in[2];
    const float* Pd    = (const float*)d_in[3];
    const float* wcap  = (const float*)d_in[4];
    const float* W1    = (const float*)d_in[5];
    const float* b1    = (const float*)d_in[6];
    const float* W2    = (const float*)d_in[7];
    const float* b2    = (const float*)d_in[8];
    const float* W3    = (const float*)d_in[9];
    const float* b3    = (const float*)d_in[10];
    float* out = (float*)d_out;

    const int B = in_sizes[0] / 4;      // x is [B, 4]
    const int blocks = B / RPB;         // 262144 / 1024 = 256

    mlp_dispatch_kernel<<<blocks, NT>>>(
        (const float4*)x, Cost, Pmax, Pd, wcap, W1, b1, W2, b2, W3, b3, out);
}